// round 1
// baseline (speedup 1.0000x reference)
#include <cuda_runtime.h>

typedef unsigned long long u64;

#define NB 1024
#define SL 512
#define NL 64

__device__ __forceinline__ u64 fma2(u64 a, u64 b, u64 c) {
    u64 d;
    asm("fma.rn.f32x2 %0, %1, %2, %3;" : "=l"(d) : "l"(a), "l"(b), "l"(c));
    return d;
}
__device__ __forceinline__ u64 add2(u64 a, u64 b) {
    u64 d;
    asm("add.rn.f32x2 %0, %1, %2;" : "=l"(d) : "l"(a), "l"(b));
    return d;
}
__device__ __forceinline__ u64 pack2(float lo, float hi) {
    u64 d;
    asm("mov.b64 %0, {%1, %2};" : "=l"(d) : "f"(lo), "f"(hi));
    return d;
}
__device__ __forceinline__ void unpack2(u64 a, float& lo, float& hi) {
    asm("mov.b64 {%0, %1}, %2;" : "=f"(lo), "=f"(hi) : "l"(a));
}

// One block = one batch element. Thread j owns label j.
// State: u = absolute score_j (fp32, grows to ~2500, fine).
// Smem (double-buffered): q_i = exp(score_i - norm) and two scalars per buffer:
//   cs[buf][0] = norm used for that q, cs[buf][1] = u_0 of that step (next norm).
// Exactly one __syncthreads per timestep.
__global__ __launch_bounds__(NL) void crf_fwd_kernel(
    const float* __restrict__ emissions,
    const int*   __restrict__ mask,
    const float* __restrict__ trans,
    const float* __restrict__ startt,
    const float* __restrict__ endt,
    float* __restrict__ out)
{
    __shared__ __align__(16) float qbuf[2][NL];
    __shared__ float cs[2][2];
    __shared__ float red[4];

    const int j = threadIdx.x;
    const int b = blockIdx.x;
    const size_t ebase = (size_t)b * SL * NL;

    // E column j: E[i][j] = exp(trans[i][j]), packed in pairs over i.
    u64 E[32];
#pragma unroll
    for (int k = 0; k < 32; k++) {
        float lo = __expf(trans[(2 * k) * NL + j]);
        float hi = __expf(trans[(2 * k + 1) * NL + j]);
        E[k] = pack2(lo, hi);
    }

    // t = 0: score = start + emissions[:,0]
    float u = startt[j] + emissions[ebase + j];
    if (j == 0) cs[0][0] = u;          // temp share of u_0 as first normalizer
    __syncthreads();
    const float z0 = cs[0][0];
    qbuf[0][j] = __expf(u - z0);
    if (j == 0) cs[0][1] = u;          // next_norm = u_0(0); cs[0][0] already = norm_used

    // prefetch t = 1
    float emit_next = emissions[ebase + NL + j];
    int   mask_next = mask[b * SL + 1];

#pragma unroll 2
    for (int t = 1; t < SL; t++) {
        __syncthreads();               // publishes buffer (t-1)&1
        const int pb = (t - 1) & 1, cb = t & 1;
        const float z  = cs[pb][0];    // normalizer of q in buffer pb
        const float zn = cs[pb][1];    // u_0^{(t-1)}: normalizer for what we publish
        const float em = emit_next;
        const int   mk = mask_next;

        int tn = t + 1; if (tn >= SL) tn = SL - 1;
        emit_next = emissions[ebase + (size_t)tn * NL + j];
        mask_next = mask[b * SL + tn];

        // s_j = sum_i q_i * E[i][j], packed f32x2, 4 accumulators
        const ulonglong2* qp = (const ulonglong2*)qbuf[pb];
        u64 a0 = 0ull, a1 = 0ull, a2 = 0ull, a3 = 0ull;
#pragma unroll
        for (int k = 0; k < 8; k++) {
            ulonglong2 v0 = qp[2 * k];
            ulonglong2 v1 = qp[2 * k + 1];
            a0 = fma2(v0.x, E[4 * k + 0], a0);
            a1 = fma2(v0.y, E[4 * k + 1], a1);
            a2 = fma2(v1.x, E[4 * k + 2], a2);
            a3 = fma2(v1.y, E[4 * k + 3], a3);
        }
        u64 aa = add2(add2(a0, a1), add2(a2, a3));
        float sx, sy;
        unpack2(aa, sx, sy);
        const float s = sx + sy;

        const float unew = em + z + __logf(s);
        if (mk) u = unew;              // mask: keep previous score when 0

        qbuf[cb][j] = __expf(u - zn);
        if (j == 0) { cs[cb][0] = zn; cs[cb][1] = u; }
    }

    // final: out[b] = logsumexp_j(u_j + end_j)
    const float v = u + endt[j];
    float m = v;
#pragma unroll
    for (int o = 16; o; o >>= 1) m = fmaxf(m, __shfl_xor_sync(0xffffffffu, m, o));
    if ((j & 31) == 0) red[j >> 5] = m;
    __syncthreads();
    m = fmaxf(red[0], red[1]);
    float ev = __expf(v - m);
#pragma unroll
    for (int o = 16; o; o >>= 1) ev += __shfl_xor_sync(0xffffffffu, ev, o);
    if ((j & 31) == 0) red[2 + (j >> 5)] = ev;
    __syncthreads();
    if (j == 0) out[b] = m + __logf(red[2] + red[3]);
}

extern "C" void kernel_launch(void* const* d_in, const int* in_sizes, int n_in,
                              void* d_out, int out_size) {
    const float* emissions = (const float*)d_in[0];
    const int*   msk       = (const int*)d_in[1];
    const float* trans     = (const float*)d_in[2];
    const float* startt    = (const float*)d_in[3];
    const float* endt      = (const float*)d_in[4];
    crf_fwd_kernel<<<NB, NL>>>(emissions, msk, trans, startt, endt, (float*)d_out);
}